// round 5
// baseline (speedup 1.0000x reference)
#include <cuda_runtime.h>
#include <math.h>

// ---------------- problem constants ----------------
#define BATCH   2
#define SEQ     512
#define NTOK    (BATCH*SEQ)          // 1024
#define DMODEL  1024
#define DINNER  2048
#define DSTATE  64
#define HEADDIM 64
#define NHEADS  32
#define CONVDIM (DINNER + 2*DSTATE)  // 2176
#define EPROJ   (2*DINNER + 2*DSTATE + NHEADS) // 4256
#define DCONV   4
#define VNUM    3
#define HORIZON 20
#define RMS_EPS 1e-5f

// ---------------- device scratch (no cudaMalloc allowed) ----------------
__device__ float g_zx [NTOK * EPROJ];    // in_proj output
__device__ float g_xc [NTOK * CONVDIM];  // conv+silu output
__device__ float g_dt [NTOK * NHEADS];   // softplus(dt)
__device__ float g_dA [NTOK * NHEADS];   // exp(dt*A)
__device__ float g_y  [NTOK * DINNER];   // scan output + D*x
__device__ float g_nrm[NTOK * DINNER];   // gated + rmsnormed
__device__ float g_h  [NTOK * DMODEL];   // out_proj output

__device__ __forceinline__ float siluf(float x) { return x / (1.0f + expf(-x)); }
__device__ __forceinline__ float softplusf(float x) {
    return (x > 20.0f) ? x : log1pf(expf(x));
}

// ---------------- SGEMM NT: C[M,N] = A[M,K] * B[N,K]^T ----------------
// A row-major MxK, B row-major NxK (K contiguous for both), C row-major MxN.
// BM=128, BN=64, BK=16, 256 threads, 8x4 per-thread microtile, global prefetch.
#define GBM 128
#define GBN 64
#define GBK 16
#define GTM 8
#define GTN 4

__global__ void __launch_bounds__(256)
sgemm_nt(const float* __restrict__ A, const float* __restrict__ B,
         float* __restrict__ C, int M, int N, int K)
{
    __shared__ __align__(16) float As[GBK][GBM + 4];
    __shared__ __align__(16) float Bs[GBK][GBN + 4];

    const int tid = threadIdx.x;
    const int tx  = tid & 15;        // n direction (16 columns of 4)
    const int ty  = tid >> 4;        // m direction (16 rows of 8)
    const int m0  = blockIdx.y * GBM;
    const int n0  = blockIdx.x * GBN;

    const int lrow = tid >> 2;       // 0..63
    const int lcol = (tid & 3) * 4;  // 0,4,8,12

    const float* Aptr = A + (size_t)(m0 + lrow) * K + lcol;
    const float* Bptr = B + (size_t)(n0 + lrow) * K + lcol;
    const bool bok = (n0 + lrow) < N;

    float acc[GTM][GTN];
#pragma unroll
    for (int i = 0; i < GTM; i++)
#pragma unroll
        for (int j = 0; j < GTN; j++) acc[i][j] = 0.0f;

    // prefetch first tile into registers
    float4 pa0 = *(const float4*)(Aptr);
    float4 pa1 = *(const float4*)(Aptr + (size_t)64 * K);
    float4 pb  = bok ? *(const float4*)(Bptr) : make_float4(0.f, 0.f, 0.f, 0.f);

    const int ntiles = K / GBK;
    for (int kt = 0; kt < ntiles; kt++) {
        // stage -> shared (transposed)
        As[lcol + 0][lrow]      = pa0.x; As[lcol + 1][lrow]      = pa0.y;
        As[lcol + 2][lrow]      = pa0.z; As[lcol + 3][lrow]      = pa0.w;
        As[lcol + 0][lrow + 64] = pa1.x; As[lcol + 1][lrow + 64] = pa1.y;
        As[lcol + 2][lrow + 64] = pa1.z; As[lcol + 3][lrow + 64] = pa1.w;
        Bs[lcol + 0][lrow] = pb.x; Bs[lcol + 1][lrow] = pb.y;
        Bs[lcol + 2][lrow] = pb.z; Bs[lcol + 3][lrow] = pb.w;
        __syncthreads();

        // prefetch next tile (overlaps with compute below)
        if (kt + 1 < ntiles) {
            const float* ap = Aptr + (size_t)(kt + 1) * GBK;
            pa0 = *(const float4*)(ap);
            pa1 = *(const float4*)(ap + (size_t)64 * K);
            pb  = bok ? *(const float4*)(Bptr + (size_t)(kt + 1) * GBK)
                      : make_float4(0.f, 0.f, 0.f, 0.f);
        }

#pragma unroll
        for (int k = 0; k < GBK; k++) {
            float4 a0 = *(const float4*)&As[k][ty * GTM];
            float4 a1 = *(const float4*)&As[k][ty * GTM + 4];
            float4 b0 = *(const float4*)&Bs[k][tx * GTN];
            float ra[8] = {a0.x, a0.y, a0.z, a0.w, a1.x, a1.y, a1.z, a1.w};
            float rb[4] = {b0.x, b0.y, b0.z, b0.w};
#pragma unroll
            for (int i = 0; i < GTM; i++)
#pragma unroll
                for (int j = 0; j < GTN; j++)
                    acc[i][j] = fmaf(ra[i], rb[j], acc[i][j]);
        }
        __syncthreads();
    }

#pragma unroll
    for (int i = 0; i < GTM; i++) {
        int m = m0 + ty * GTM + i;
        int n = n0 + tx * GTN;
        if (n + 3 < N) {
            *(float4*)&C[(size_t)m * N + n] =
                make_float4(acc[i][0], acc[i][1], acc[i][2], acc[i][3]);
        } else {
#pragma unroll
            for (int j = 0; j < GTN; j++)
                if (n + j < N) C[(size_t)m * N + n + j] = acc[i][j];
        }
    }
}

// ---------------- conv (depthwise causal, width 4) + silu ----------------
__global__ void __launch_bounds__(256)
conv_silu_kernel(const float* __restrict__ conv_w, const float* __restrict__ conv_b)
{
    int idx = blockIdx.x * blockDim.x + threadIdx.x;
    if (idx >= NTOK * CONVDIM) return;
    int c = idx % CONVDIM;
    int t = idx / CONVDIM;
    int s = t & (SEQ - 1);
    int b = t >> 9;

    float acc = conv_b[c];
#pragma unroll
    for (int k = 0; k < DCONV; k++) {
        int ss = s + k - (DCONV - 1);
        if (ss >= 0)
            acc = fmaf(conv_w[c * DCONV + k],
                       g_zx[(size_t)(b * SEQ + ss) * EPROJ + DINNER + c], acc);
    }
    g_xc[(size_t)t * CONVDIM + c] = siluf(acc);
}

// ---------------- dt = softplus(dt_raw + bias), dA = exp(dt*A) ----------------
__global__ void __launch_bounds__(256)
dt_kernel(const float* __restrict__ dt_bias, const float* __restrict__ A_log)
{
    int idx = blockIdx.x * blockDim.x + threadIdx.x;
    if (idx >= NTOK * NHEADS) return;
    int hh = idx & (NHEADS - 1);
    int t  = idx >> 5;
    float raw = g_zx[(size_t)t * EPROJ + DINNER + CONVDIM + hh];
    float dtv = softplusf(raw + dt_bias[hh]);
    float Ah  = -expf(A_log[hh]);
    g_dt[idx] = dtv;
    g_dA[idx] = expf(dtv * Ah);
}

// ---------------- selective scan ----------------
// grid: (4, NHEADS, BATCH); block: 128 threads.
// Block owns 16 p-rows; thread (lp = t>>3) owns p = pb+lp, 8 n-values (n0 = (t&7)*8).
__global__ void __launch_bounds__(128)
scan_kernel(const float* __restrict__ Dp)
{
    const int b  = blockIdx.z;
    const int hh = blockIdx.y;
    const int pb = blockIdx.x * 16;
    const int t  = threadIdx.x;
    const int lp = t >> 3;
    const int n0 = (t & 7) * 8;

    __shared__ __align__(16) float sB[32][64];
    __shared__ __align__(16) float sC[32][64];
    __shared__ __align__(16) float sX[32][16];
    __shared__ float sdA[32], sdt[32];

    float hst[8];
#pragma unroll
    for (int j = 0; j < 8; j++) hst[j] = 0.0f;

    const float Dh = Dp[hh];
    const size_t rowbase = (size_t)(b * SEQ) * CONVDIM;

    for (int c = 0; c < SEQ / 32; c++) {
        const int s0 = c * 32;
        // stage B and C (32 steps x 64 states)
        for (int i = t; i < 512; i += 128) {
            int si = i >> 4, j4 = (i & 15) * 4;
            size_t r = rowbase + (size_t)(s0 + si) * CONVDIM;
            *(float4*)&sB[si][j4] = *(const float4*)&g_xc[r + DINNER + j4];
            *(float4*)&sC[si][j4] = *(const float4*)&g_xc[r + DINNER + DSTATE + j4];
        }
        // stage x (32 steps x 16 p)
        {
            int i = t;  // exactly 128 float4s
            int si = i >> 2, j4 = (i & 3) * 4;
            size_t r = rowbase + (size_t)(s0 + si) * CONVDIM;
            *(float4*)&sX[si][j4] =
                *(const float4*)&g_xc[r + hh * HEADDIM + pb + j4];
        }
        if (t < 32) {
            int idx = (b * SEQ + s0 + t) * NHEADS + hh;
            sdA[t] = g_dA[idx];
            sdt[t] = g_dt[idx];
        }
        __syncthreads();

        for (int si = 0; si < 32; si++) {
            float dAv = sdA[si];
            float xv  = sX[si][lp];
            float dtx = sdt[si] * xv;
            float4 b0 = *(const float4*)&sB[si][n0];
            float4 b1 = *(const float4*)&sB[si][n0 + 4];
            float4 c0 = *(const float4*)&sC[si][n0];
            float4 c1 = *(const float4*)&sC[si][n0 + 4];
            float yp;
            hst[0] = fmaf(hst[0], dAv, dtx * b0.x); yp  = hst[0] * c0.x;
            hst[1] = fmaf(hst[1], dAv, dtx * b0.y); yp += hst[1] * c0.y;
            hst[2] = fmaf(hst[2], dAv, dtx * b0.z); yp += hst[2] * c0.z;
            hst[3] = fmaf(hst[3], dAv, dtx * b0.w); yp += hst[3] * c0.w;
            hst[4] = fmaf(hst[4], dAv, dtx * b1.x); yp += hst[4] * c1.x;
            hst[5] = fmaf(hst[5], dAv, dtx * b1.y); yp += hst[5] * c1.y;
            hst[6] = fmaf(hst[6], dAv, dtx * b1.z); yp += hst[6] * c1.z;
            hst[7] = fmaf(hst[7], dAv, dtx * b1.w); yp += hst[7] * c1.w;
            // reduce across the 8 lanes sharing this p
            yp += __shfl_xor_sync(0xffffffffu, yp, 1);
            yp += __shfl_xor_sync(0xffffffffu, yp, 2);
            yp += __shfl_xor_sync(0xffffffffu, yp, 4);
            if ((t & 7) == 0)
                g_y[(size_t)(b * SEQ + s0 + si) * DINNER + hh * HEADDIM + pb + lp] =
                    yp + Dh * xv;
        }
        __syncthreads();
    }
}

// ---------------- gate (silu(z)) + RMSNorm ----------------
__global__ void __launch_bounds__(256)
gate_norm_kernel(const float* __restrict__ norm_w)
{
    const int t = blockIdx.x;
    __shared__ float sg[DINNER];
    __shared__ float ssum[8];

    float local = 0.0f;
    for (int i = threadIdx.x; i < DINNER; i += 256) {
        float z = g_zx[(size_t)t * EPROJ + i];
        float g = g_y[(size_t)t * DINNER + i] * siluf(z);
        sg[i] = g;
        local = fmaf(g, g, local);
    }
#pragma unroll
    for (int off = 16; off; off >>= 1)
        local += __shfl_xor_sync(0xffffffffu, local, off);
    if ((threadIdx.x & 31) == 0) ssum[threadIdx.x >> 5] = local;
    __syncthreads();
    if (threadIdx.x < 8) {
        float v = ssum[threadIdx.x];
#pragma unroll
        for (int off = 4; off; off >>= 1)
            v += __shfl_xor_sync(0xffu, v, off);
        if (threadIdx.x == 0) ssum[0] = v;
    }
    __syncthreads();
    float scale = rsqrtf(ssum[0] / (float)DINNER + RMS_EPS);
    for (int i = threadIdx.x; i < DINNER; i += 256)
        g_nrm[(size_t)t * DINNER + i] = sg[i] * scale * norm_w[i];
}

// ---------------- decoders ----------------
// pred_current: one warp per (token, v) output. grid 768 x 128 threads.
__global__ void __launch_bounds__(128)
dec_cur_kernel(const float* __restrict__ w, const float* __restrict__ bias,
               float* __restrict__ out)
{
    int o = blockIdx.x * 4 + (threadIdx.x >> 5);   // 0..3071
    int lane = threadIdx.x & 31;
    int tok = o / VNUM, v = o % VNUM;
    const float* hr = &g_h[(size_t)tok * DMODEL];
    const float* wr = &w[v * DMODEL];
    float acc = 0.0f;
    for (int d = lane; d < DMODEL; d += 32) acc = fmaf(hr[d], wr[d], acc);
#pragma unroll
    for (int off = 16; off; off >>= 1)
        acc += __shfl_xor_sync(0xffffffffu, acc, off);
    if (lane == 0) out[o] = acc + bias[v];
}

// pred_future: one warp per (b, j) output, j in [0,60). grid 30 x 128 threads.
__global__ void __launch_bounds__(128)
dec_fut_kernel(const float* __restrict__ w, const float* __restrict__ bias,
               float* __restrict__ out)
{
    int o = blockIdx.x * 4 + (threadIdx.x >> 5);   // 0..119
    int lane = threadIdx.x & 31;
    int b = o / (HORIZON * VNUM), j = o % (HORIZON * VNUM);
    const float* hr = &g_h[(size_t)(b * SEQ + (SEQ - 1)) * DMODEL];
    const float* wr = &w[j * DMODEL];
    float acc = 0.0f;
    for (int d = lane; d < DMODEL; d += 32) acc = fmaf(hr[d], wr[d], acc);
#pragma unroll
    for (int off = 16; off; off >>= 1)
        acc += __shfl_xor_sync(0xffffffffu, acc, off);
    if (lane == 0) out[BATCH * SEQ * VNUM + o] = acc + bias[j];
}

// ---------------- launch ----------------
extern "C" void kernel_launch(void* const* d_in, const int* in_sizes, int n_in,
                              void* d_out, int out_size)
{
    const float* embed      = (const float*)d_in[0];
    const float* in_proj_w  = (const float*)d_in[1];
    const float* conv_w     = (const float*)d_in[2];
    const float* conv_b     = (const float*)d_in[3];
    const float* dt_bias    = (const float*)d_in[4];
    const float* A_log      = (const float*)d_in[5];
    const float* Dp         = (const float*)d_in[6];
    const float* norm_w     = (const float*)d_in[7];
    const float* out_proj_w = (const float*)d_in[8];
    const float* dec_cur_w  = (const float*)d_in[9];
    const float* dec_cur_b  = (const float*)d_in[10];
    const float* dec_fut_w  = (const float*)d_in[11];
    const float* dec_fut_b  = (const float*)d_in[12];
    float* out = (float*)d_out;

    float *zx, *nrm, *h;
    cudaGetSymbolAddress((void**)&zx,  g_zx);
    cudaGetSymbolAddress((void**)&nrm, g_nrm);
    cudaGetSymbolAddress((void**)&h,   g_h);

    // 1) in_proj: [1024,1024] x [4256,1024]^T -> [1024,4256]
    {
        dim3 grid((EPROJ + GBN - 1) / GBN, NTOK / GBM);
        sgemm_nt<<<grid, 256>>>(embed, in_proj_w, zx, NTOK, EPROJ, DMODEL);
    }
    // 2) causal conv + silu
    conv_silu_kernel<<<(NTOK * CONVDIM + 255) / 256, 256>>>(conv_w, conv_b);
    // 3) dt / dA
    dt_kernel<<<(NTOK * NHEADS + 255) / 256, 256>>>(dt_bias, A_log);
    // 4) selective scan (+ D*x)
    {
        dim3 grid(4, NHEADS, BATCH);
        scan_kernel<<<grid, 128>>>(Dp);
    }
    // 5) gate + rmsnorm
    gate_norm_kernel<<<NTOK, 256>>>(norm_w);
    // 6) out_proj: [1024,2048] x [1024,2048]^T -> [1024,1024]
    {
        dim3 grid(DMODEL / GBN, NTOK / GBM);
        sgemm_nt<<<grid, 256>>>(nrm, out_proj_w, h, NTOK, DMODEL, DINNER);
    }
    // 7) decoders
    dec_cur_kernel<<<(NTOK * VNUM) / 4, 128>>>(dec_cur_w, dec_cur_b, out);
    dec_fut_kernel<<<(BATCH * HORIZON * VNUM) / 4, 128>>>(dec_fut_w, dec_fut_b, out);
}